// round 4
// baseline (speedup 1.0000x reference)
#include <cuda_runtime.h>

// Inputs: (8,3,512,512) fp32 x3 (general, ir, vi). Output: 1 float (mean L1).
#define WD   512
#define HT   512
#define NPL  24          // N*C planes per image
#define CT   128         // output cols per block
#define ABW  138         // CT + 10
#define XW   148         // CT + 20
#define NTH  448         // 14 warps
#define NWARP (NTH/32)
#define BANDA 172        // bands: 172,172,168

constexpr float EPSV   = 1e-6f;
constexpr float INV_KK = 1.0f / 121.0f;
constexpr int   EPLANE = WD * HT;
constexpr float SCALE  = 1.0f / (float)(NPL * EPLANE);

// ---- shared layout (float units) ------------------------------------------
constexpr int OFF_ROWX = 0;                       // [3][2][XW]
constexpr int SZ_ROWX  = 3 * 2 * XW;              // 888
constexpr int OFF_HC   = OFF_ROWX + SZ_ROWX;      // [3][12][ABW] float2
constexpr int SZ_HC    = 3 * 12 * ABW * 2;        // 9936
constexpr int OFF_AB   = OFF_HC + SZ_HC;          // [3][2][ABW] float2
constexpr int SZ_AB    = 3 * 2 * ABW * 2;         // 1656
constexpr int OFF_HAC  = OFF_AB + SZ_AB;          // [3][12][CT] float2
constexpr int SZ_HAC   = 3 * 12 * CT * 2;         // 9216
constexpr int OFF_MAM  = OFF_HAC + SZ_HAC;        // [3][2][CT] float2
constexpr int SZ_MAM   = 3 * 2 * CT * 2;          // 1536
constexpr int OFF_RED  = OFF_MAM + SZ_MAM;
constexpr int SMEM_FLOATS = OFF_RED + NWARP;      // 23246
constexpr int SMEM_BYTES  = SMEM_FLOATS * 4;      // ~93 KB -> 2 blocks/SM

__global__ void __launch_bounds__(NTH) fused_loss(
    const float* __restrict__ gen, const float* __restrict__ ir,
    const float* __restrict__ vi, float* __restrict__ out)
{
    extern __shared__ float smf[];
    const int t    = threadIdx.x;
    const int c0   = blockIdx.x * CT;
    const int y0   = blockIdx.y * BANDA;
    const int band = (blockIdx.y == 2) ? (HT - 2 * BANDA) : BANDA;  // 172/172/168
    const size_t pbase = (size_t)blockIdx.z * EPLANE;
    const float* xin[3] = { ir + pbase, vi + pbase, gen + pbase };

    float*  rowx = smf + OFF_ROWX;                 // [p][r][XW]
    float2* hc   = (float2*)(smf + OFF_HC);        // [p][slot12][ABW]
    float2* ab   = (float2*)(smf + OFF_AB);        // [p][r][ABW]
    float2* hac  = (float2*)(smf + OFF_HAC);       // [p][slot12][CT]
    float2* mam  = (float2*)(smf + OFF_MAM);       // [p][r][CT]
    float*  red  = smf + OFF_RED;

    // role decode (fixed per thread)
    const int p2p   = t / ABW;                     // phase-2 plane (valid if t < 414)
    const int p2c   = t - p2p * ABW;               // phase-2 column
    const int p3p   = t >> 7;                      // phase-3a plane (valid if t < 384)
    const int p3c   = t & (CT - 1);                // phase-3a column
    const int lbr   = t >> 7;                      // loss row (valid if t < 256)
    const int lbc   = t & (CT - 1);

    float S1 = 0.f, S2 = 0.f;                      // stage-1 vertical running sums
    float T1 = 0.f, T2 = 0.f;                      // stage-2 vertical running sums
    float lacc = 0.f;

    const int iters = (band + 20) >> 1;            // 96 or 94
    int rowcur = y0 - 10;

    for (int it = 0; it < iters; ++it, rowcur += 2) {
        // ---- P1: load 2 rows x 3 planes x XW (zero-padded) ----------------
#pragma unroll
        for (int i = 0; i < 2; ++i) {
            const int j = t + i * NTH;
            if (j < 3 * 2 * XW) {
                const int p   = j / (2 * XW);
                const int rem = j - p * (2 * XW);
                const int r   = rem / XW;
                const int c   = rem - r * XW;
                const int row = rowcur + r;
                const int col = c0 - 10 + c;
                float v = 0.f;
                if (((unsigned)row < (unsigned)HT) && ((unsigned)col < (unsigned)WD))
                    v = __ldg(xin[p] + (size_t)row * WD + col);
                rowx[j] = v;
            }
        }
        __syncthreads();

        // ---- P2: horizontal 11-tap of x,x^2; vertical running sums; ab ----
        if (t < 3 * ABW) {
            const float* rxp = rowx + p2p * (2 * XW);
#pragma unroll
            for (int r = 0; r < 2; ++r) {
                const int yi = rowcur + r;
                float s1 = 0.f, s2 = 0.f;
#pragma unroll
                for (int k = 0; k < 11; ++k) {
                    float u = rxp[r * XW + p2c + k];
                    s1 += u;
                    s2 = fmaf(u, u, s2);
                }
                S1 += s1; S2 += s2;
                if (yi >= y0 + 1) {                        // row yi-11 leaves window
                    float2 o = hc[(p2p * 12 + ((yi + 13) % 12)) * ABW + p2c];
                    S1 -= o.x; S2 -= o.y;
                }
                hc[(p2p * 12 + ((yi + 24) % 12)) * ABW + p2c] = make_float2(s1, s2);
                if (yi >= y0) {
                    const int ya    = yi - 5;
                    const int colab = c0 - 5 + p2c;
                    float2 v = make_float2(0.f, 0.f);
                    if (((unsigned)ya < (unsigned)HT) && ((unsigned)colab < (unsigned)WD)) {
                        float mean = S1 * INV_KK;
                        float corr = S2 * INV_KK;
                        float var  = corr - mean * mean;
                        float aa   = var / (var + EPSV);
                        v = make_float2(aa, mean - aa * mean);
                    }
                    ab[(p2p * 2 + r) * ABW + p2c] = v;
                }
            }
        }
        __syncthreads();

        // ---- P3a: horizontal 11-tap of a,b; vertical running sums; means --
        if (t < 3 * CT) {
#pragma unroll
            for (int r = 0; r < 2; ++r) {
                const int yi = rowcur + r;
                if (yi >= y0) {
                    const int ya = yi - 5;
                    const float2* abp = ab + (p3p * 2 + r) * ABW;
                    float h1 = 0.f, h2 = 0.f;
#pragma unroll
                    for (int k = 0; k < 11; ++k) {
                        float2 u = abp[p3c + k];
                        h1 += u.x; h2 += u.y;
                    }
                    T1 += h1; T2 += h2;
                    if (ya >= y0 + 6) {                    // ab row ya-11 leaves window
                        float2 o = hac[(p3p * 12 + ((ya + 13) % 12)) * CT + p3c];
                        T1 -= o.x; T2 -= o.y;
                    }
                    hac[(p3p * 12 + ((ya + 24) % 12)) * CT + p3c] = make_float2(h1, h2);
                    if (ya - 5 >= y0)
                        mam[(p3p * 2 + r) * CT + p3c] =
                            make_float2(T1 * INV_KK, T2 * INV_KK);
                }
            }
        }
        __syncthreads();

        // ---- P3b: combine with x (global re-read) + loss ------------------
        if (t < 2 * CT) {
            const int yo = rowcur + lbr - 10;
            if (yo >= y0 && yo < y0 + band) {
                float f[3];
#pragma unroll
                for (int p = 0; p < 3; ++p) {
                    float xv = __ldg(xin[p] + (size_t)yo * WD + c0 + lbc);
                    float2 m = mam[(p * 2 + lbr) * CT + lbc];
                    f[p] = xv - fmaf(m.x, xv, m.y);
                }
                lacc += fabsf(f[2] - fmaxf(fabsf(f[0]), fabsf(f[1])));
            }
        }
        // no barrier needed here: next P1 touches only rowx; next writes to
        // ab/mam happen after the next iteration's barriers.
    }

    // ---- block reduction + atomic ----------------------------------------
#pragma unroll
    for (int o = 16; o; o >>= 1) lacc += __shfl_down_sync(0xffffffffu, lacc, o);
    if ((t & 31) == 0) red[t >> 5] = lacc;
    __syncthreads();
    if (t == 0) {
        float v = 0.f;
#pragma unroll
        for (int w = 0; w < NWARP; ++w) v += red[w];
        atomicAdd(out, v * SCALE);
    }
}

__global__ void zero_out(float* out) { out[0] = 0.f; }

// ---------------------------------------------------------------------------
extern "C" void kernel_launch(void* const* d_in, const int* in_sizes, int n_in,
                              void* d_out, int out_size) {
    const float* gen = (const float*)d_in[0];
    const float* ir  = (const float*)d_in[1];
    const float* vi  = (const float*)d_in[2];
    float* out = (float*)d_out;

    cudaFuncSetAttribute(fused_loss, cudaFuncAttributeMaxDynamicSharedMemorySize,
                         SMEM_BYTES);

    zero_out<<<1, 1>>>(out);
    dim3 grid(WD / CT, 3, NPL);   // (4, 3, 24) = 288 blocks, bands 172/172/168
    fused_loss<<<grid, NTH, SMEM_BYTES>>>(gen, ir, vi, out);
}

// round 5
// speedup vs baseline: 1.3371x; 1.3371x over previous
#include <cuda_runtime.h>

// Inputs: (8,3,512,512) fp32 x3 (general, ir, vi). Output: 1 float (mean L1).
#define WD   512
#define HT   512
#define NPL  24          // N*C planes per image
#define CT   128         // output cols per block
#define ABW  138         // CT + 10
#define XW   148         // CT + 20
#define NTH  512         // 16 warps
#define NWARP 16
#define BANDA 172        // bands: 172,172,168
#define RPB  4           // rows ingested per iteration

constexpr float EPSV   = 1e-6f;
constexpr float INV_KK = 1.0f / 121.0f;
constexpr int   EPLANE = WD * HT;
constexpr float SCALE  = 1.0f / (float)(NPL * EPLANE);

// ---- shared layout (float units) ------------------------------------------
constexpr int OFF_ROWX = 0;                       // [3][RPB][XW]
constexpr int SZ_ROWX  = 3 * RPB * XW;            // 1776
constexpr int OFF_HC   = OFF_ROWX + SZ_ROWX;      // [3][12][ABW] float2
constexpr int SZ_HC    = 3 * 12 * ABW * 2;        // 9936
constexpr int OFF_AB   = OFF_HC + SZ_HC;          // [3][RPB][ABW] float2
constexpr int SZ_AB    = 3 * RPB * ABW * 2;       // 3312
constexpr int OFF_HAC  = OFF_AB + SZ_AB;          // [3][12][CT] float2
constexpr int SZ_HAC   = 3 * 12 * CT * 2;         // 9216
constexpr int OFF_MAM  = OFF_HAC + SZ_HAC;        // [3][RPB][CT] float2
constexpr int SZ_MAM   = 3 * RPB * CT * 2;        // 3072
constexpr int OFF_RED  = OFF_MAM + SZ_MAM;
constexpr int SMEM_FLOATS = OFF_RED + NWARP;      // 27328
constexpr int SMEM_BYTES  = SMEM_FLOATS * 4;      // 109312 B -> 2 blocks/SM

__global__ void __launch_bounds__(NTH, 2) fused_loss(
    const float* __restrict__ gen, const float* __restrict__ ir,
    const float* __restrict__ vi, float* __restrict__ out)
{
    extern __shared__ float smf[];
    const int t    = threadIdx.x;
    const int c0   = blockIdx.x * CT;
    const int y0   = blockIdx.y * BANDA;
    const int band = (blockIdx.y == 2) ? (HT - 2 * BANDA) : BANDA;  // 172/172/168
    const size_t pbase = (size_t)blockIdx.z * EPLANE;
    const float* xin[3] = { ir + pbase, vi + pbase, gen + pbase };

    float*  rowx = smf + OFF_ROWX;                 // [p][r][XW]
    float2* hc   = (float2*)(smf + OFF_HC);        // [p][slot12][ABW]
    float2* ab   = (float2*)(smf + OFF_AB);        // [p][r][ABW]
    float2* hac  = (float2*)(smf + OFF_HAC);       // [p][slot12][CT]
    float2* mam  = (float2*)(smf + OFF_MAM);       // [p][r][CT]
    float*  red  = smf + OFF_RED;

    // fixed per-thread roles
    const int p2p = t / ABW;                       // phase-2 plane (t < 414)
    const int p2c = t - p2p * ABW;                 // phase-2 column
    const int p3p = t >> 7;                        // phase-3a plane (t < 384)
    const int p3c = t & (CT - 1);
    const int lr  = t >> 7;                        // phase-3b row 0..3 (all 512)
    const int lc  = t & (CT - 1);

    float S1 = 0.f, S2 = 0.f;                      // stage-1 vertical running sums
    float T1 = 0.f, T2 = 0.f;                      // stage-2 vertical running sums
    float lacc = 0.f;

    const int iters = (band + 20) / RPB;           // 48 or 47
    int rowcur = y0 - 10;

    float rin[4];
    // preamble ingest load (rows rowcur..rowcur+3)
    {
        const int rb = rowcur;
#pragma unroll
        for (int i = 0; i < 4; ++i) {
            const int j = t + i * NTH;
            float v = 0.f;
            if (j < 3 * RPB * XW) {
                const int p   = j / (RPB * XW);
                const int rem = j - p * (RPB * XW);
                const int r   = rem / XW;
                const int c   = rem - r * XW;
                const int row = rb + r;
                const int col = c0 - 10 + c;
                if (((unsigned)row < (unsigned)HT) && ((unsigned)col < (unsigned)WD))
                    v = __ldg(xin[p] + (size_t)row * WD + col);
            }
            rin[i] = v;
        }
    }

    for (int it = 0; it < iters; ++it) {
        // ---- prefetch P3b x (emit rows rowcur-10+lr), consumed after 3 bars
        float xpre[3] = {0.f, 0.f, 0.f};
        const int yo = rowcur - 10 + lr;
        const bool emitOK = (yo >= y0) && (yo < y0 + band);
        if (emitOK) {
#pragma unroll
            for (int p = 0; p < 3; ++p)
                xpre[p] = __ldg(xin[p] + (size_t)yo * WD + c0 + lc);
        }

        // ---- store this iteration's ingest rows ---------------------------
#pragma unroll
        for (int i = 0; i < 4; ++i) {
            const int j = t + i * NTH;
            if (j < 3 * RPB * XW) rowx[j] = rin[i];
        }

        // ---- prefetch next iteration's ingest rows ------------------------
        {
            const int rb = rowcur + RPB;
#pragma unroll
            for (int i = 0; i < 4; ++i) {
                const int j = t + i * NTH;
                float v = 0.f;
                if (j < 3 * RPB * XW) {
                    const int p   = j / (RPB * XW);
                    const int rem = j - p * (RPB * XW);
                    const int r   = rem / XW;
                    const int c   = rem - r * XW;
                    const int row = rb + r;
                    const int col = c0 - 10 + c;
                    if (((unsigned)row < (unsigned)HT) && ((unsigned)col < (unsigned)WD))
                        v = __ldg(xin[p] + (size_t)row * WD + col);
                }
                rin[i] = v;
            }
        }
        __syncthreads();

        // ---- P2: horizontal 11-tap of x,x^2; vertical running sums; ab ----
        if (t < 3 * ABW) {
            int slot = (rowcur + 24) % 12;         // slot(yi) = (yi+24)%12
#pragma unroll
            for (int r = 0; r < RPB; ++r) {
                const int yi = rowcur + r;
                const float* rp = rowx + (p2p * RPB + r) * XW;
                float s1 = 0.f, s2 = 0.f;
#pragma unroll
                for (int k = 0; k < 11; ++k) {
                    float u = rp[p2c + k];
                    s1 += u;
                    s2 = fmaf(u, u, s2);
                }
                S1 += s1; S2 += s2;
                if (yi >= y0 + 1) {                // row yi-11 leaves window
                    int so = slot + 1; if (so >= 12) so -= 12;
                    float2 o = hc[(p2p * 12 + so) * ABW + p2c];
                    S1 -= o.x; S2 -= o.y;
                }
                hc[(p2p * 12 + slot) * ABW + p2c] = make_float2(s1, s2);
                if (yi >= y0) {
                    const int ya    = yi - 5;
                    const int colab = c0 - 5 + p2c;
                    float2 v = make_float2(0.f, 0.f);
                    if (((unsigned)ya < (unsigned)HT) && ((unsigned)colab < (unsigned)WD)) {
                        float mean = S1 * INV_KK;
                        float corr = S2 * INV_KK;
                        float var  = corr - mean * mean;
                        float aa   = var / (var + EPSV);
                        v = make_float2(aa, mean - aa * mean);
                    }
                    ab[(p2p * RPB + r) * ABW + p2c] = v;
                }
                ++slot; if (slot >= 12) slot -= 12;
            }
        }
        __syncthreads();

        // ---- P3a: horizontal 11-tap of a,b; vertical running sums; means --
        if (t < 3 * CT) {
            int slot = (rowcur + 19) % 12;         // slot(ya)=(ya+24)%12, ya=rowcur-5
#pragma unroll
            for (int r = 0; r < RPB; ++r) {
                const int yi = rowcur + r;
                if (yi >= y0) {
                    const int ya = yi - 5;
                    const float2* ap = ab + (p3p * RPB + r) * ABW;
                    float h1 = 0.f, h2 = 0.f;
#pragma unroll
                    for (int k = 0; k < 11; ++k) {
                        float2 u = ap[p3c + k];
                        h1 += u.x; h2 += u.y;
                    }
                    T1 += h1; T2 += h2;
                    if (ya >= y0 + 6) {            // ab row ya-11 leaves window
                        int so = slot + 1; if (so >= 12) so -= 12;
                        float2 o = hac[(p3p * 12 + so) * CT + p3c];
                        T1 -= o.x; T2 -= o.y;
                    }
                    hac[(p3p * 12 + slot) * CT + p3c] = make_float2(h1, h2);
                    if (ya - 5 >= y0)
                        mam[(p3p * RPB + r) * CT + p3c] =
                            make_float2(T1 * INV_KK, T2 * INV_KK);
                }
                ++slot; if (slot >= 12) slot -= 12;
            }
        }
        __syncthreads();

        // ---- P3b: combine prefetched x with means + loss ------------------
        if (emitOK) {
            float f[3];
#pragma unroll
            for (int p = 0; p < 3; ++p) {
                float2 m = mam[(p * RPB + lr) * CT + lc];
                f[p] = xpre[p] - fmaf(m.x, xpre[p], m.y);
            }
            lacc += fabsf(f[2] - fmaxf(fabsf(f[0]), fabsf(f[1])));
        }
        // no trailing barrier: next iteration's stores hit rowx (readers done
        // before bar2) and mam/ab writers are separated by >=2 barriers.
        rowcur += RPB;
    }

    // ---- block reduction + atomic ----------------------------------------
#pragma unroll
    for (int o = 16; o; o >>= 1) lacc += __shfl_down_sync(0xffffffffu, lacc, o);
    if ((t & 31) == 0) red[t >> 5] = lacc;
    __syncthreads();
    if (t == 0) {
        float v = 0.f;
#pragma unroll
        for (int w = 0; w < NWARP; ++w) v += red[w];
        atomicAdd(out, v * SCALE);
    }
}

__global__ void zero_out(float* out) { out[0] = 0.f; }

// ---------------------------------------------------------------------------
extern "C" void kernel_launch(void* const* d_in, const int* in_sizes, int n_in,
                              void* d_out, int out_size) {
    const float* gen = (const float*)d_in[0];
    const float* ir  = (const float*)d_in[1];
    const float* vi  = (const float*)d_in[2];
    float* out = (float*)d_out;

    cudaFuncSetAttribute(fused_loss, cudaFuncAttributeMaxDynamicSharedMemorySize,
                         SMEM_BYTES);

    zero_out<<<1, 1>>>(out);
    dim3 grid(WD / CT, 3, NPL);   // (4, 3, 24) = 288 blocks, bands 172/172/168
    fused_loss<<<grid, NTH, SMEM_BYTES>>>(gen, ir, vi, out);
}

// round 6
// speedup vs baseline: 1.4586x; 1.0909x over previous
#include <cuda_runtime.h>

// Inputs: (8,3,512,512) fp32 x3 (general, ir, vi). Output: 1 float (mean L1).
#define WD   512
#define HT   512
#define NPL  24
#define CT   128         // output cols per block
#define CTP  64          // output col pairs
#define ABP  70          // ab col pairs (138 real cols padded to 140)
#define ABW2 140
#define XW2  152         // 148 real + 4 zero pad
#define NTH  384         // 12 warps
#define NWARP 12
#define BANDA 172        // bands: 172,172,168
#define RPB  4
#define NING (3*RPB*XW2) // 1824

constexpr float EPSV   = 1e-6f;
constexpr float INV_KK = 1.0f / 121.0f;
constexpr int   EPLANE = WD * HT;
constexpr float SCALE  = 1.0f / (float)(NPL * EPLANE);

// ---- shared layout (float units, all offsets 16B aligned) -----------------
constexpr int OFF_ROWX = 0;                       // [3][RPB][XW2] float
constexpr int OFF_HC   = 1824;                    // [3][12][ABP] float4
constexpr int OFF_AB   = 11904;                   // [3][RPB][ABP] float4
constexpr int OFF_HAC  = 15264;                   // [3][12][CTP] float4
constexpr int OFF_MAM  = 24480;                   // [3][RPB][CTP] float4
constexpr int OFF_RED  = 27552;
constexpr int SMEM_FLOATS = OFF_RED + NWARP;      // 27564
constexpr int SMEM_BYTES  = SMEM_FLOATS * 4;      // 110256 B -> 2 blocks/SM

__global__ void __launch_bounds__(NTH, 2) fused_loss(
    const float* __restrict__ gen, const float* __restrict__ ir,
    const float* __restrict__ vi, float* __restrict__ out)
{
    extern __shared__ float smf[];
    const int t    = threadIdx.x;
    const int c0   = blockIdx.x * CT;
    const int y0   = blockIdx.y * BANDA;
    const int band = (blockIdx.y == 2) ? (HT - 2 * BANDA) : BANDA;
    const size_t pbase = (size_t)blockIdx.z * EPLANE;
    const float* xin[3] = { ir + pbase, vi + pbase, gen + pbase };

    float*  rowx  = smf + OFF_ROWX;
    float4* hc4   = (float4*)(smf + OFF_HC);       // [p][slot12][ABP]
    float4* ab4   = (float4*)(smf + OFF_AB);       // [p][r][ABP]
    float4* hac4  = (float4*)(smf + OFF_HAC);      // [p][slot12][CTP]
    float4* mam4  = (float4*)(smf + OFF_MAM);      // [p][r][CTP]
    float2* mamf2 = (float2*)(smf + OFF_MAM);      // same, per-column view
    float*  red   = smf + OFF_RED;

    // fixed roles
    const int p2p = t / ABP;                       // phase-2 plane (t < 210)
    const int p2j = t - p2p * ABP;                 // phase-2 col pair
    const int p3p = t >> 6;                        // phase-3a plane (t < 192)
    const int p3i = t & (CTP - 1);                 // phase-3a col pair
    const int lrA = t >> 7;                        // P3b pixel A row 0..2
    const int lc  = t & (CT - 1);

    float S1[2] = {0,0}, S2[2] = {0,0};
    float T1[2] = {0,0}, T2[2] = {0,0};
    float lacc = 0.f;

    const int iters = (band + 20) / RPB;           // 48 or 47
    int rowcur = y0 - 10;

    float rin[5];
    // preamble ingest (rows rowcur..rowcur+3)
#pragma unroll
    for (int i = 0; i < 5; ++i) {
        const int j = t + i * NTH;
        float v = 0.f;
        if (j < NING) {
            const int p   = j / (RPB * XW2);
            const int rem = j - p * (RPB * XW2);
            const int r   = rem / XW2;
            const int c   = rem - r * XW2;
            const int row = rowcur + r;
            const int col = c0 - 10 + c;
            if (c < 148 && ((unsigned)row < (unsigned)HT) && ((unsigned)col < (unsigned)WD))
                v = __ldg(xin[p] + (size_t)row * WD + col);
        }
        rin[i] = v;
    }

    for (int it = 0; it < iters; ++it) {
        // ---- P3b prefetch: emit rows rowcur-10 .. rowcur-7 ---------------
        const int yoA = rowcur - 10 + lrA;                 // rows 0..2
        const int yoB = rowcur - 7;                        // row 3 (t<128)
        const bool okA = (yoA >= y0) && (yoA < y0 + band);
        const bool okB = (t < CT) && (yoB >= y0) && (yoB < y0 + band);
        float xpA[3], xpB[3];
        if (okA) {
#pragma unroll
            for (int p = 0; p < 3; ++p)
                xpA[p] = __ldg(xin[p] + (size_t)yoA * WD + c0 + lc);
        }
        if (okB) {
#pragma unroll
            for (int p = 0; p < 3; ++p)
                xpB[p] = __ldg(xin[p] + (size_t)yoB * WD + c0 + lc);
        }

        // ---- store current ingest, prefetch next -------------------------
#pragma unroll
        for (int i = 0; i < 5; ++i) {
            const int j = t + i * NTH;
            if (j < NING) rowx[j] = rin[i];
        }
        {
            const int rb = rowcur + RPB;
#pragma unroll
            for (int i = 0; i < 5; ++i) {
                const int j = t + i * NTH;
                float v = 0.f;
                if (j < NING) {
                    const int p   = j / (RPB * XW2);
                    const int rem = j - p * (RPB * XW2);
                    const int r   = rem / XW2;
                    const int c   = rem - r * XW2;
                    const int row = rb + r;
                    const int col = c0 - 10 + c;
                    if (c < 148 && ((unsigned)row < (unsigned)HT) && ((unsigned)col < (unsigned)WD))
                        v = __ldg(xin[p] + (size_t)row * WD + col);
                }
                rin[i] = v;
            }
        }
        __syncthreads();

        // ---- P2: 12-wide sums of x, x^2 per col pair; vertical rings; ab --
        if (t < 3 * ABP) {
            int slot = (rowcur + 24) % 12;
#pragma unroll
            for (int r = 0; r < RPB; ++r) {
                const int yi = rowcur + r;
                const float2* rp2 = ((const float2*)rowx)
                                    + (p2p * RPB + r) * (XW2 / 2) + p2j;
                float2 v0 = rp2[0], v1 = rp2[1], v2 = rp2[2];
                float2 v3 = rp2[3], v4 = rp2[4], v5 = rp2[5];
                float s1 = ((v0.x + v0.y) + (v1.x + v1.y))
                         + ((v2.x + v2.y) + (v3.x + v3.y))
                         + ((v4.x + v4.y) + (v5.x + v5.y));
                float s2 = 0.f;
                s2 = fmaf(v0.x, v0.x, s2); s2 = fmaf(v0.y, v0.y, s2);
                s2 = fmaf(v1.x, v1.x, s2); s2 = fmaf(v1.y, v1.y, s2);
                s2 = fmaf(v2.x, v2.x, s2); s2 = fmaf(v2.y, v2.y, s2);
                s2 = fmaf(v3.x, v3.x, s2); s2 = fmaf(v3.y, v3.y, s2);
                s2 = fmaf(v4.x, v4.x, s2); s2 = fmaf(v4.y, v4.y, s2);
                s2 = fmaf(v5.x, v5.x, s2); s2 = fmaf(v5.y, v5.y, s2);
                const float s1a = s1 - v5.y, s1b = s1 - v0.x;
                const float s2a = fmaf(-v5.y, v5.y, s2);
                const float s2b = fmaf(-v0.x, v0.x, s2);
                S1[0] += s1a; S2[0] += s2a; S1[1] += s1b; S2[1] += s2b;
                if (yi >= y0 + 1) {
                    int so = slot + 1; if (so >= 12) so -= 12;
                    float4 o = hc4[(p2p * 12 + so) * ABP + p2j];
                    S1[0] -= o.x; S2[0] -= o.y; S1[1] -= o.z; S2[1] -= o.w;
                }
                hc4[(p2p * 12 + slot) * ABP + p2j] = make_float4(s1a, s2a, s1b, s2b);
                if (yi >= y0) {
                    const int ya   = yi - 5;
                    const int colb = c0 - 5 + 2 * p2j;
                    float4 v = make_float4(0.f, 0.f, 0.f, 0.f);
                    if ((unsigned)ya < (unsigned)HT) {
                        if ((unsigned)colb < (unsigned)WD) {
                            float mean = S1[0] * INV_KK;
                            float corr = S2[0] * INV_KK;
                            float var  = corr - mean * mean;
                            float aa   = var / (var + EPSV);
                            v.x = aa; v.y = mean - aa * mean;
                        }
                        if ((unsigned)(colb + 1) < (unsigned)WD) {
                            float mean = S1[1] * INV_KK;
                            float corr = S2[1] * INV_KK;
                            float var  = corr - mean * mean;
                            float aa   = var / (var + EPSV);
                            v.z = aa; v.w = mean - aa * mean;
                        }
                    }
                    ab4[(p2p * RPB + r) * ABP + p2j] = v;
                }
                ++slot; if (slot >= 12) slot -= 12;
            }
        }
        __syncthreads();

        // ---- P3a: 12-wide sums of a,b per col pair; vertical rings; means -
        if (t < 3 * CTP) {
            int slot = (rowcur + 19) % 12;
#pragma unroll
            for (int r = 0; r < RPB; ++r) {
                const int yi = rowcur + r;
                if (yi >= y0) {
                    const int ya = yi - 5;
                    const float4* ap = ab4 + (p3p * RPB + r) * ABP + p3i;
                    float4 w0 = ap[0], w1 = ap[1], w2 = ap[2];
                    float4 w3 = ap[3], w4 = ap[4], w5 = ap[5];
                    float h1 = ((w0.x + w0.z) + (w1.x + w1.z))
                             + ((w2.x + w2.z) + (w3.x + w3.z))
                             + ((w4.x + w4.z) + (w5.x + w5.z));
                    float h2 = ((w0.y + w0.w) + (w1.y + w1.w))
                             + ((w2.y + w2.w) + (w3.y + w3.w))
                             + ((w4.y + w4.w) + (w5.y + w5.w));
                    const float h1a = h1 - w5.z, h2a = h2 - w5.w;
                    const float h1b = h1 - w0.x, h2b = h2 - w0.y;
                    T1[0] += h1a; T2[0] += h2a; T1[1] += h1b; T2[1] += h2b;
                    if (ya >= y0 + 6) {
                        int so = slot + 1; if (so >= 12) so -= 12;
                        float4 o = hac4[(p3p * 12 + so) * CTP + p3i];
                        T1[0] -= o.x; T2[0] -= o.y; T1[1] -= o.z; T2[1] -= o.w;
                    }
                    hac4[(p3p * 12 + slot) * CTP + p3i] = make_float4(h1a, h2a, h1b, h2b);
                    if (ya - 5 >= y0)
                        mam4[(p3p * RPB + r) * CTP + p3i] =
                            make_float4(T1[0] * INV_KK, T2[0] * INV_KK,
                                        T1[1] * INV_KK, T2[1] * INV_KK);
                }
                ++slot; if (slot >= 12) slot -= 12;
            }
        }
        __syncthreads();

        // ---- P3b: combine prefetched x with means + loss ------------------
        if (okA) {
            float f[3];
#pragma unroll
            for (int p = 0; p < 3; ++p) {
                float2 m = mamf2[(p * RPB + lrA) * CT + lc];
                f[p] = xpA[p] - fmaf(m.x, xpA[p], m.y);
            }
            lacc += fabsf(f[2] - fmaxf(fabsf(f[0]), fabsf(f[1])));
        }
        if (okB) {
            float f[3];
#pragma unroll
            for (int p = 0; p < 3; ++p) {
                float2 m = mamf2[(p * RPB + 3) * CT + lc];
                f[p] = xpB[p] - fmaf(m.x, xpB[p], m.y);
            }
            lacc += fabsf(f[2] - fmaxf(fabsf(f[0]), fabsf(f[1])));
        }
        rowcur += RPB;
    }

    // ---- block reduction + atomic ----------------------------------------
#pragma unroll
    for (int o = 16; o; o >>= 1) lacc += __shfl_down_sync(0xffffffffu, lacc, o);
    if ((t & 31) == 0) red[t >> 5] = lacc;
    __syncthreads();
    if (t == 0) {
        float v = 0.f;
#pragma unroll
        for (int w = 0; w < NWARP; ++w) v += red[w];
        atomicAdd(out, v * SCALE);
    }
}

__global__ void zero_out(float* out) { out[0] = 0.f; }

// ---------------------------------------------------------------------------
extern "C" void kernel_launch(void* const* d_in, const int* in_sizes, int n_in,
                              void* d_out, int out_size) {
    const float* gen = (const float*)d_in[0];
    const float* ir  = (const float*)d_in[1];
    const float* vi  = (const float*)d_in[2];
    float* out = (float*)d_out;

    cudaFuncSetAttribute(fused_loss, cudaFuncAttributeMaxDynamicSharedMemorySize,
                         SMEM_BYTES);

    zero_out<<<1, 1>>>(out);
    dim3 grid(WD / CT, 3, NPL);   // (4, 3, 24) = 288 blocks
    fused_loss<<<grid, NTH, SMEM_BYTES>>>(gen, ir, vi, out);
}

// round 7
// speedup vs baseline: 1.5132x; 1.0374x over previous
#include <cuda_runtime.h>

// Inputs: (8,3,512,512) fp32 x3 (general, ir, vi). Output: 1 float (mean L1).
#define WD   512
#define HT   512
#define NPL  24
#define CT   128         // output cols per block
#define CTP  64          // output col pairs
#define ABP  69          // ab col pairs (138 cols)
#define NTH  512         // 16 warps
#define NWARP 16
#define BANDA 172        // bands: 172,172,168
#define RPB  4

constexpr float EPSV   = 1e-6f;
constexpr float INV_KK = 1.0f / 121.0f;
constexpr int   EPLANE = WD * HT;
constexpr float SCALE  = 1.0f / (float)(NPL * EPLANE);

// ---- shared layout (float units; every offset 16B aligned) ----------------
constexpr int OFF_HC   = 0;                       // [3][11][ABP] float4 = 9108
constexpr int OFF_AB   = 9108;                    // [2][3][RPB][ABP] float4 = 6624
constexpr int OFF_HAC  = 15732;                   // [3][11][CTP] float4 = 8448
constexpr int OFF_MAM  = 24180;                   // [3][RPB][CTP] float4 = 3072
constexpr int OFF_RED  = 27252;
constexpr int SMEM_FLOATS = OFF_RED + NWARP;      // 27268
constexpr int SMEM_BYTES  = SMEM_FLOATS * 4;      // 109072 B -> 2 blocks/SM

__global__ void __launch_bounds__(NTH, 2) fused_loss(
    const float* __restrict__ gen, const float* __restrict__ ir,
    const float* __restrict__ vi, float* __restrict__ out)
{
    extern __shared__ float smf[];
    const int t    = threadIdx.x;
    const int c0   = blockIdx.x * CT;
    const int y0   = blockIdx.y * BANDA;
    const int band = (blockIdx.y == 2) ? (HT - 2 * BANDA) : BANDA;
    const size_t pbase = (size_t)blockIdx.z * EPLANE;
    const float* xin[3] = { ir + pbase, vi + pbase, gen + pbase };

    float4* hc4   = (float4*)(smf + OFF_HC);       // [p][slot11][ABP]
    float4* ab4   = (float4*)(smf + OFF_AB);       // [buf][p][r][ABP]
    float4* hac4  = (float4*)(smf + OFF_HAC);      // [p][slot11][CTP]
    float4* mam4  = (float4*)(smf + OFF_MAM);      // [p][r][CTP]
    float2* mamf2 = (float2*)(smf + OFF_MAM);
    float*  red   = smf + OFF_RED;

    // roles: group A = warps 0..6 (P2), group B = warps 8..13 (P3a)
    const bool isA = t < 3 * ABP;                  // 207 threads
    const int  p2p = t / ABP;
    const int  p2j = t - p2p * ABP;
    const int  ub  = t - 256;
    const bool isB = (ub >= 0) && (ub < 3 * CTP);  // 192 threads
    const int  p3p = ub >> 6;
    const int  p3i = ub & (CTP - 1);
    const int  lr  = t >> 7;                       // P3b row 0..3
    const int  lc  = t & (CT - 1);

    float S1[2] = {0,0}, S2[2] = {0,0};            // P2 vertical running sums
    float T1[2] = {0,0}, T2[2] = {0,0};            // P3a vertical running sums
    float lacc = 0.f;

    const int iters = (band + 20) / RPB + 1;       // 49 or 48

    for (int i = 0; i < iters; ++i) {
        const int Rb = y0 - 10 + 4 * i;            // P2 batch base row

        // ---- P3b prefetch (rows y0-24+4i+lr), consumed after barA --------
        const int yo  = y0 - 24 + 4 * i + lr;
        const bool okE = (yo >= y0) && (yo < y0 + band);
        float xp0, xp1, xp2;
        if (okE) {
            const size_t gi = (size_t)yo * WD + c0 + lc;
            xp0 = __ldg(xin[0] + gi);
            xp1 = __ldg(xin[1] + gi);
            xp2 = __ldg(xin[2] + gi);
        }

        // ================= phase A (parallel P2 | P3a) ====================
        if (isA && i < iters - 1) {
            // P2: batch i, rows Rb..Rb+3, x from global
            const float* xp   = xin[p2p];
            const int    colb = c0 - 10 + 2 * p2j;
            int slot = (Rb + 22) % 11;
            float4* abw = ab4 + (i & 1) * (3 * RPB * ABP) + (p2p * RPB) * ABP + p2j;
#pragma unroll
            for (int r = 0; r < RPB; ++r) {
                const int yi = Rb + r;
                float2 v0, v1, v2, v3, v4, v5;
                if ((unsigned)yi < (unsigned)HT) {
                    const float* rowp = xp + (size_t)yi * WD;
                    v0 = ((unsigned)(colb)      < (unsigned)WD) ? __ldg((const float2*)(rowp + colb))      : make_float2(0.f,0.f);
                    v1 = ((unsigned)(colb + 2)  < (unsigned)WD) ? __ldg((const float2*)(rowp + colb + 2))  : make_float2(0.f,0.f);
                    v2 = ((unsigned)(colb + 4)  < (unsigned)WD) ? __ldg((const float2*)(rowp + colb + 4))  : make_float2(0.f,0.f);
                    v3 = ((unsigned)(colb + 6)  < (unsigned)WD) ? __ldg((const float2*)(rowp + colb + 6))  : make_float2(0.f,0.f);
                    v4 = ((unsigned)(colb + 8)  < (unsigned)WD) ? __ldg((const float2*)(rowp + colb + 8))  : make_float2(0.f,0.f);
                    v5 = ((unsigned)(colb + 10) < (unsigned)WD) ? __ldg((const float2*)(rowp + colb + 10)) : make_float2(0.f,0.f);
                } else {
                    v0 = v1 = v2 = v3 = v4 = v5 = make_float2(0.f, 0.f);
                }
                float s1 = ((v0.x + v0.y) + (v1.x + v1.y))
                         + ((v2.x + v2.y) + (v3.x + v3.y))
                         + ((v4.x + v4.y) + (v5.x + v5.y));
                float s2 = 0.f;
                s2 = fmaf(v0.x, v0.x, s2); s2 = fmaf(v0.y, v0.y, s2);
                s2 = fmaf(v1.x, v1.x, s2); s2 = fmaf(v1.y, v1.y, s2);
                s2 = fmaf(v2.x, v2.x, s2); s2 = fmaf(v2.y, v2.y, s2);
                s2 = fmaf(v3.x, v3.x, s2); s2 = fmaf(v3.y, v3.y, s2);
                s2 = fmaf(v4.x, v4.x, s2); s2 = fmaf(v4.y, v4.y, s2);
                s2 = fmaf(v5.x, v5.x, s2); s2 = fmaf(v5.y, v5.y, s2);
                const float s1a = s1 - v5.y, s1b = s1 - v0.x;
                const float s2a = fmaf(-v5.y, v5.y, s2);
                const float s2b = fmaf(-v0.x, v0.x, s2);
                // ring: read h(yi-11) then overwrite with h(yi) (same slot)
                float4* rp = &hc4[(p2p * 11 + slot) * ABP + p2j];
                if (yi >= y0 + 1) {
                    float4 o = *rp;
                    S1[0] -= o.x; S2[0] -= o.y; S1[1] -= o.z; S2[1] -= o.w;
                }
                *rp = make_float4(s1a, s2a, s1b, s2b);
                S1[0] += s1a; S2[0] += s2a; S1[1] += s1b; S2[1] += s2b;
                if (yi >= y0) {
                    const int ya = yi - 5;
                    const int cb = c0 - 5 + 2 * p2j;
                    float4 v = make_float4(0.f, 0.f, 0.f, 0.f);
                    if ((unsigned)ya < (unsigned)HT) {
                        if ((unsigned)cb < (unsigned)WD) {
                            float mean = S1[0] * INV_KK;
                            float var  = S2[0] * INV_KK - mean * mean;
                            float aa   = var / (var + EPSV);
                            v.x = aa; v.y = mean - aa * mean;
                        }
                        if ((unsigned)(cb + 1) < (unsigned)WD) {
                            float mean = S1[1] * INV_KK;
                            float var  = S2[1] * INV_KK - mean * mean;
                            float aa   = var / (var + EPSV);
                            v.z = aa; v.w = mean - aa * mean;
                        }
                    }
                    abw[r * ABP] = v;
                }
                slot = (slot + 1 == 11) ? 0 : slot + 1;
            }
        }
        if (isB) {
            // P3a: batch i-1, ab rows yi2 = Rb-4+r (buffer (i-1)&1)
            const float4* abr = ab4 + ((i - 1) & 1) * (3 * RPB * ABP)
                                + (p3p * RPB) * ABP + p3i;
            int slot = (Rb + 13) % 11;                 // slot(ya), ya = Rb-9+r
#pragma unroll
            for (int r = 0; r < RPB; ++r) {
                const int yi2 = Rb - 4 + r;
                if (yi2 >= y0) {
                    const int ya = yi2 - 5;
                    const float4* ap = abr + r * ABP;
                    float4 w0 = ap[0], w1 = ap[1], w2 = ap[2];
                    float4 w3 = ap[3], w4 = ap[4], w5 = ap[5];
                    float h1 = ((w0.x + w0.z) + (w1.x + w1.z))
                             + ((w2.x + w2.z) + (w3.x + w3.z))
                             + ((w4.x + w4.z) + (w5.x + w5.z));
                    float h2 = ((w0.y + w0.w) + (w1.y + w1.w))
                             + ((w2.y + w2.w) + (w3.y + w3.w))
                             + ((w4.y + w4.w) + (w5.y + w5.w));
                    const float h1a = h1 - w5.z, h2a = h2 - w5.w;
                    const float h1b = h1 - w0.x, h2b = h2 - w0.y;
                    float4* rp = &hac4[(p3p * 11 + slot) * CTP + p3i];
                    if (ya >= y0 + 6) {
                        float4 o = *rp;
                        T1[0] -= o.x; T2[0] -= o.y; T1[1] -= o.z; T2[1] -= o.w;
                    }
                    *rp = make_float4(h1a, h2a, h1b, h2b);
                    T1[0] += h1a; T2[0] += h2a; T1[1] += h1b; T2[1] += h2b;
                    if (ya - 5 >= y0)
                        mam4[(p3p * RPB + r) * CTP + p3i] =
                            make_float4(T1[0] * INV_KK, T2[0] * INV_KK,
                                        T1[1] * INV_KK, T2[1] * INV_KK);
                }
                slot = (slot + 1 == 11) ? 0 : slot + 1;
            }
        }
        __syncthreads();

        // ================= phase B: P3b (all threads) =====================
        if (okE) {
            float2 m0 = mamf2[(0 * RPB + lr) * CT + lc];
            float2 m1 = mamf2[(1 * RPB + lr) * CT + lc];
            float2 m2 = mamf2[(2 * RPB + lr) * CT + lc];
            float f0 = xp0 - fmaf(m0.x, xp0, m0.y);
            float f1 = xp1 - fmaf(m1.x, xp1, m1.y);
            float f2 = xp2 - fmaf(m2.x, xp2, m2.y);
            lacc += fabsf(f2 - fmaxf(fabsf(f0), fabsf(f1)));
        }
        __syncthreads();
    }

    // ---- block reduction + atomic ----------------------------------------
#pragma unroll
    for (int o = 16; o; o >>= 1) lacc += __shfl_down_sync(0xffffffffu, lacc, o);
    if ((t & 31) == 0) red[t >> 5] = lacc;
    __syncthreads();
    if (t == 0) {
        float v = 0.f;
#pragma unroll
        for (int w = 0; w < NWARP; ++w) v += red[w];
        atomicAdd(out, v * SCALE);
    }
}

__global__ void zero_out(float* out) { out[0] = 0.f; }

// ---------------------------------------------------------------------------
extern "C" void kernel_launch(void* const* d_in, const int* in_sizes, int n_in,
                              void* d_out, int out_size) {
    const float* gen = (const float*)d_in[0];
    const float* ir  = (const float*)d_in[1];
    const float* vi  = (const float*)d_in[2];
    float* out = (float*)d_out;

    cudaFuncSetAttribute(fused_loss, cudaFuncAttributeMaxDynamicSharedMemorySize,
                         SMEM_BYTES);

    zero_out<<<1, 1>>>(out);
    dim3 grid(WD / CT, 3, NPL);   // (4, 3, 24) = 288 blocks
    fused_loss<<<grid, NTH, SMEM_BYTES>>>(gen, ir, vi, out);
}

// round 8
// speedup vs baseline: 1.7043x; 1.1263x over previous
#include <cuda_runtime.h>

// Inputs: (8,3,512,512) fp32 x3 (general, ir, vi). Output: 1 float (mean L1).
#define WD   512
#define HT   512
#define NPL  24
#define CT   128         // output cols per block
#define CTP  64          // output col pairs
#define ABP  69          // ab col pairs (138 cols)
#define NTH  448         // 14 warps
#define NWARP 14
#define BANDA 172        // bands: 172,172,168
#define RPB  4

constexpr float EPSV   = 1e-6f;
constexpr float INV_KK = 1.0f / 121.0f;
constexpr int   EPLANE = WD * HT;
constexpr float SCALE  = 1.0f / (float)(NPL * EPLANE);

// ---- shared layout (float units; 16B-aligned offsets) ---------------------
constexpr int OFF_HC   = 0;                       // [3][11][ABP] float4 = 9108
constexpr int OFF_AB   = 9108;                    // [2][3][RPB][ABP] float4 = 6624
constexpr int OFF_HAC  = 15732;                   // [3][11][CTP] float4 = 8448
constexpr int OFF_FB   = 24180;                   // [2][2][RPB][CTP] float2 = 2048
constexpr int OFF_RED  = 26228;
constexpr int SMEM_FLOATS = OFF_RED + NWARP;      // 26242
constexpr int SMEM_BYTES  = SMEM_FLOATS * 4;      // 104968 B -> 2 blocks/SM

__global__ void __launch_bounds__(NTH, 2) fused_loss(
    const float* __restrict__ gen, const float* __restrict__ ir,
    const float* __restrict__ vi, float* __restrict__ out)
{
    extern __shared__ float smf[];
    const int t    = threadIdx.x;
    const int c0   = blockIdx.x * CT;
    const int y0   = blockIdx.y * BANDA;
    const int band = (blockIdx.y == 2) ? (HT - 2 * BANDA) : BANDA;
    const size_t pbase = (size_t)blockIdx.z * EPLANE;
    const float* xin[3] = { ir + pbase, vi + pbase, gen + pbase };

    float4* hc4  = (float4*)(smf + OFF_HC);        // [p][slot11][ABP]
    float4* ab4  = (float4*)(smf + OFF_AB);        // [buf][p][r][ABP]
    float4* hac4 = (float4*)(smf + OFF_HAC);       // [p][slot11][CTP]
    float2* fb2  = (float2*)(smf + OFF_FB);        // [buf][p01][r][CTP]
    float*  red  = smf + OFF_RED;

    // roles: P2 = threads 0..206 (warps 0..6), P3a = threads 224..415 (warps 7..12)
    const bool isA = t < 3 * ABP;                  // 207 threads
    const int  p2p = t / ABP;
    const int  p2j = t - p2p * ABP;
    const int  tb  = t - 224;
    const bool isB = (tb >= 0) && (tb < 3 * CTP);  // 192 threads
    const int  p3p = tb >> 6;
    const int  p3i = tb & (CTP - 1);

    float S1[2] = {0,0}, S2[2] = {0,0};            // P2 vertical running sums
    float T1[2] = {0,0}, T2[2] = {0,0};            // P3a vertical running sums
    float2 f2s[4] = {{0,0},{0,0},{0,0},{0,0}};     // plane-2 f carry (1 iter)
    float lacc = 0.f;

    const int iters = (band + 24) / RPB + 1;       // 50 or 49
    const int pmax  = (band + 20) / RPB;           // P2 active while i < pmax

    for (int i = 0; i < iters; ++i) {
        const int Rb = y0 - 10 + 4 * i;            // P2 batch base row

        // ================= P2: batch i =====================================
        if (isA && i < pmax) {
            const float* xp   = xin[p2p];
            const int    colb = c0 - 10 + 2 * p2j;
            int slot = (Rb + 22) % 11;
            float4* abw = ab4 + (i & 1) * (3 * RPB * ABP) + (p2p * RPB) * ABP + p2j;
#pragma unroll
            for (int r = 0; r < RPB; ++r) {
                const int yi = Rb + r;
                float2 v0, v1, v2, v3, v4, v5;
                if ((unsigned)yi < (unsigned)HT) {
                    const float* rowp = xp + (size_t)yi * WD;
                    v0 = ((unsigned)(colb)      < (unsigned)WD) ? __ldg((const float2*)(rowp + colb))      : make_float2(0.f,0.f);
                    v1 = ((unsigned)(colb + 2)  < (unsigned)WD) ? __ldg((const float2*)(rowp + colb + 2))  : make_float2(0.f,0.f);
                    v2 = ((unsigned)(colb + 4)  < (unsigned)WD) ? __ldg((const float2*)(rowp + colb + 4))  : make_float2(0.f,0.f);
                    v3 = ((unsigned)(colb + 6)  < (unsigned)WD) ? __ldg((const float2*)(rowp + colb + 6))  : make_float2(0.f,0.f);
                    v4 = ((unsigned)(colb + 8)  < (unsigned)WD) ? __ldg((const float2*)(rowp + colb + 8))  : make_float2(0.f,0.f);
                    v5 = ((unsigned)(colb + 10) < (unsigned)WD) ? __ldg((const float2*)(rowp + colb + 10)) : make_float2(0.f,0.f);
                } else {
                    v0 = v1 = v2 = v3 = v4 = v5 = make_float2(0.f, 0.f);
                }
                float s1 = ((v0.x + v0.y) + (v1.x + v1.y))
                         + ((v2.x + v2.y) + (v3.x + v3.y))
                         + ((v4.x + v4.y) + (v5.x + v5.y));
                float s2 = 0.f;
                s2 = fmaf(v0.x, v0.x, s2); s2 = fmaf(v0.y, v0.y, s2);
                s2 = fmaf(v1.x, v1.x, s2); s2 = fmaf(v1.y, v1.y, s2);
                s2 = fmaf(v2.x, v2.x, s2); s2 = fmaf(v2.y, v2.y, s2);
                s2 = fmaf(v3.x, v3.x, s2); s2 = fmaf(v3.y, v3.y, s2);
                s2 = fmaf(v4.x, v4.x, s2); s2 = fmaf(v4.y, v4.y, s2);
                s2 = fmaf(v5.x, v5.x, s2); s2 = fmaf(v5.y, v5.y, s2);
                const float s1a = s1 - v5.y, s1b = s1 - v0.x;
                const float s2a = fmaf(-v5.y, v5.y, s2);
                const float s2b = fmaf(-v0.x, v0.x, s2);
                float4* rp = &hc4[(p2p * 11 + slot) * ABP + p2j];
                if (yi >= y0 + 1) {
                    float4 o = *rp;
                    S1[0] -= o.x; S2[0] -= o.y; S1[1] -= o.z; S2[1] -= o.w;
                }
                *rp = make_float4(s1a, s2a, s1b, s2b);
                S1[0] += s1a; S2[0] += s2a; S1[1] += s1b; S2[1] += s2b;
                if (yi >= y0) {
                    const int ya = yi - 5;
                    const int cb = c0 - 5 + 2 * p2j;
                    float4 v = make_float4(0.f, 0.f, 0.f, 0.f);
                    if ((unsigned)ya < (unsigned)HT) {
                        if ((unsigned)cb < (unsigned)WD) {
                            float mean = S1[0] * INV_KK;
                            float var  = S2[0] * INV_KK - mean * mean;
                            float aa   = var / (var + EPSV);
                            v.x = aa; v.y = mean - aa * mean;
                        }
                        if ((unsigned)(cb + 1) < (unsigned)WD) {
                            float mean = S1[1] * INV_KK;
                            float var  = S2[1] * INV_KK - mean * mean;
                            float aa   = var / (var + EPSV);
                            v.z = aa; v.w = mean - aa * mean;
                        }
                    }
                    abw[r * ABP] = v;
                }
                slot = (slot + 1 == 11) ? 0 : slot + 1;
            }
        }

        // ================= P3a: batch i-1 + f + loss =======================
        if (isB) {
            // x prefetch for output rows Rb-14+r
            const float* xp = xin[p3p];
            const int    cx = c0 + 2 * p3i;
            float2 xv[4];
#pragma unroll
            for (int r = 0; r < RPB; ++r) {
                const int yo = Rb - 14 + r;
                xv[r] = (yo >= y0 && yo < y0 + band)
                      ? __ldg((const float2*)(xp + (size_t)yo * WD + cx))
                      : make_float2(0.f, 0.f);
            }

            // plane-2: combine batch i-2 (register f2s + fbuf written last iter)
            if (p3p == 2) {
                const float2* fa = fb2 + (((i - 1) & 1) * 2 + 0) * (RPB * CTP) + p3i;
                const float2* fbv = fb2 + (((i - 1) & 1) * 2 + 1) * (RPB * CTP) + p3i;
#pragma unroll
                for (int r = 0; r < RPB; ++r) {
                    const int yr = 4 * i - 28 + r;
                    if (yr >= 0 && yr < band) {
                        float2 a01 = fa[r * CTP];
                        float2 b01 = fbv[r * CTP];
                        lacc += fabsf(f2s[r].x - fmaxf(a01.x, b01.x));
                        lacc += fabsf(f2s[r].y - fmaxf(a01.y, b01.y));
                    }
                }
            }

            const float4* abr = ab4 + ((i - 1) & 1) * (3 * RPB * ABP)
                                + (p3p * RPB) * ABP + p3i;
            int slot = (Rb + 13) % 11;                 // slot(ya), ya = Rb-9+r
#pragma unroll
            for (int r = 0; r < RPB; ++r) {
                const int yb = Rb - 4 + r;
                if (yb >= y0 && yb <= y0 + band + 9) {
                    const int ya = yb - 5;
                    const float4* ap = abr + r * ABP;
                    float4 w0 = ap[0], w1 = ap[1], w2 = ap[2];
                    float4 w3 = ap[3], w4 = ap[4], w5 = ap[5];
                    float h1 = ((w0.x + w0.z) + (w1.x + w1.z))
                             + ((w2.x + w2.z) + (w3.x + w3.z))
                             + ((w4.x + w4.z) + (w5.x + w5.z));
                    float h2 = ((w0.y + w0.w) + (w1.y + w1.w))
                             + ((w2.y + w2.w) + (w3.y + w3.w))
                             + ((w4.y + w4.w) + (w5.y + w5.w));
                    const float h1a = h1 - w5.z, h2a = h2 - w5.w;
                    const float h1b = h1 - w0.x, h2b = h2 - w0.y;
                    float4* rp = &hac4[(p3p * 11 + slot) * CTP + p3i];
                    if (ya >= y0 + 6) {
                        float4 o = *rp;
                        T1[0] -= o.x; T2[0] -= o.y; T1[1] -= o.z; T2[1] -= o.w;
                    }
                    *rp = make_float4(h1a, h2a, h1b, h2b);
                    T1[0] += h1a; T2[0] += h2a; T1[1] += h1b; T2[1] += h2b;
                    const int yo = ya - 5;
                    if (yo >= y0 && yo < y0 + band) {
                        float ma0 = T1[0] * INV_KK, mb0 = T2[0] * INV_KK;
                        float ma1 = T1[1] * INV_KK, mb1 = T2[1] * INV_KK;
                        float2 xr = xv[r];
                        float f0 = xr.x - fmaf(ma0, xr.x, mb0);
                        float f1 = xr.y - fmaf(ma1, xr.y, mb1);
                        if (p3p < 2) {
                            fb2[(((i & 1) * 2 + p3p) * RPB + r) * CTP + p3i] =
                                make_float2(fabsf(f0), fabsf(f1));
                        } else {
                            f2s[r] = make_float2(f0, f1);
                        }
                    }
                }
                slot = (slot + 1 == 11) ? 0 : slot + 1;
            }
        }
        __syncthreads();
    }

    // ---- block reduction + atomic ----------------------------------------
#pragma unroll
    for (int o = 16; o; o >>= 1) lacc += __shfl_down_sync(0xffffffffu, lacc, o);
    if ((t & 31) == 0) red[t >> 5] = lacc;
    __syncthreads();
    if (t == 0) {
        float v = 0.f;
#pragma unroll
        for (int w = 0; w < NWARP; ++w) v += red[w];
        atomicAdd(out, v * SCALE);
    }
}

__global__ void zero_out(float* out) { out[0] = 0.f; }

// ---------------------------------------------------------------------------
extern "C" void kernel_launch(void* const* d_in, const int* in_sizes, int n_in,
                              void* d_out, int out_size) {
    const float* gen = (const float*)d_in[0];
    const float* ir  = (const float*)d_in[1];
    const float* vi  = (const float*)d_in[2];
    float* out = (float*)d_out;

    cudaFuncSetAttribute(fused_loss, cudaFuncAttributeMaxDynamicSharedMemorySize,
                         SMEM_BYTES);

    zero_out<<<1, 1>>>(out);
    dim3 grid(WD / CT, 3, NPL);   // (4, 3, 24) = 288 blocks
    fused_loss<<<grid, NTH, SMEM_BYTES>>>(gen, ir, vi, out);
}

// round 10
// speedup vs baseline: 1.9159x; 1.1242x over previous
#include <cuda_runtime.h>

// Inputs: (8,3,512,512) fp32 x3 (general, ir, vi). Output: 1 float (mean L1).
#define WD   512
#define HT   512
#define NPL  24
#define CT   128         // output cols per block
#define CTP  64          // output col pairs
#define ABP  69          // ab col pairs (138 cols)
#define NTH  448         // 14 warps
#define NWARP 14
#define BANDA 172        // bands: 172,172,168
#define RPB  4

constexpr float EPSV   = 1e-6f;
constexpr float INV_KK = 1.0f / 121.0f;
constexpr int   EPLANE = WD * HT;
constexpr float SCALE  = 1.0f / (float)(NPL * EPLANE);

// ---- shared layout (float units; 16B-aligned offsets) ---------------------
constexpr int OFF_HC   = 0;                       // [3][11][ABP] float4 = 9108
constexpr int OFF_AB   = 9108;                    // [2][3][RPB][ABP] float4 = 6624
constexpr int OFF_HAC  = 15732;                   // [3][11][CTP] float4 = 8448
constexpr int OFF_FB   = 24180;                   // [2][2][RPB][CTP] float2 = 2048
constexpr int OFF_RED  = 26228;
constexpr int SMEM_FLOATS = OFF_RED + NWARP;      // 26242
constexpr int SMEM_BYTES  = SMEM_FLOATS * 4;      // 104968 B -> 2 blocks/SM

__device__ __forceinline__ float fast_rcp(float x) {
    float r;
    asm("rcp.approx.f32 %0, %1;" : "=f"(r) : "f"(x));
    return r;
}

struct IterState {
    float S1[2], S2[2];          // P2 vertical running sums
    float T1[2], T2[2];          // P3a vertical running sums
    float2 f2s[4];               // plane-2 f carry (1 iter)
    float lacc;
};

// One pipeline iteration. STEADY=true drops all row-range predicates (proven
// always-true for i in [7, iSteadyEnd)).
template <bool STEADY>
__device__ __forceinline__ void iter_body(
    int i, int y0, int band, int c0, int pmax,
    bool isA, int p2p, int p2j, bool isB, int p3p, int p3i,
    bool okc0, bool okc1, bool okc2, bool okc3, bool okc4, bool okc5,
    bool okab0, bool okab1,
    const float* const* xin,
    float4* hc4, float4* ab4, float4* hac4, float2* fb2,
    IterState& st)
{
    const int Rb = y0 - 10 + 4 * i;

    // ================= P2: batch i =========================================
    if (isA && (STEADY || i < pmax)) {
        const float* xp   = xin[p2p];
        const int    colb = c0 - 10 + 2 * p2j;
        int slot = (Rb + 22) % 11;
        float4* abw = ab4 + (i & 1) * (3 * RPB * ABP) + (p2p * RPB) * ABP + p2j;
#pragma unroll
        for (int r = 0; r < RPB; ++r) {
            const int yi = Rb + r;
            float2 v0, v1, v2, v3, v4, v5;
            if (STEADY || (unsigned)yi < (unsigned)HT) {
                const float* rowp = xp + (size_t)yi * WD;
                v0 = okc0 ? __ldg((const float2*)(rowp + colb))      : make_float2(0.f,0.f);
                v1 = okc1 ? __ldg((const float2*)(rowp + colb + 2))  : make_float2(0.f,0.f);
                v2 = okc2 ? __ldg((const float2*)(rowp + colb + 4))  : make_float2(0.f,0.f);
                v3 = okc3 ? __ldg((const float2*)(rowp + colb + 6))  : make_float2(0.f,0.f);
                v4 = okc4 ? __ldg((const float2*)(rowp + colb + 8))  : make_float2(0.f,0.f);
                v5 = okc5 ? __ldg((const float2*)(rowp + colb + 10)) : make_float2(0.f,0.f);
            } else {
                v0 = v1 = v2 = v3 = v4 = v5 = make_float2(0.f, 0.f);
            }
            float s1 = ((v0.x + v0.y) + (v1.x + v1.y))
                     + ((v2.x + v2.y) + (v3.x + v3.y))
                     + ((v4.x + v4.y) + (v5.x + v5.y));
            float s2 = 0.f;
            s2 = fmaf(v0.x, v0.x, s2); s2 = fmaf(v0.y, v0.y, s2);
            s2 = fmaf(v1.x, v1.x, s2); s2 = fmaf(v1.y, v1.y, s2);
            s2 = fmaf(v2.x, v2.x, s2); s2 = fmaf(v2.y, v2.y, s2);
            s2 = fmaf(v3.x, v3.x, s2); s2 = fmaf(v3.y, v3.y, s2);
            s2 = fmaf(v4.x, v4.x, s2); s2 = fmaf(v4.y, v4.y, s2);
            s2 = fmaf(v5.x, v5.x, s2); s2 = fmaf(v5.y, v5.y, s2);
            const float s1a = s1 - v5.y, s1b = s1 - v0.x;
            const float s2a = fmaf(-v5.y, v5.y, s2);
            const float s2b = fmaf(-v0.x, v0.x, s2);
            float4* rp = &hc4[(p2p * 11 + slot) * ABP + p2j];
            if (STEADY || yi >= y0 + 1) {
                float4 o = *rp;
                st.S1[0] -= o.x; st.S2[0] -= o.y; st.S1[1] -= o.z; st.S2[1] -= o.w;
            }
            *rp = make_float4(s1a, s2a, s1b, s2b);
            st.S1[0] += s1a; st.S2[0] += s2a; st.S1[1] += s1b; st.S2[1] += s2b;
            if (STEADY || yi >= y0) {
                const int ya = yi - 5;
                float4 v = make_float4(0.f, 0.f, 0.f, 0.f);
                if (STEADY || (unsigned)ya < (unsigned)HT) {
                    if (okab0) {
                        float mean = st.S1[0] * INV_KK;
                        float var  = st.S2[0] * INV_KK - mean * mean;
                        float rr   = fast_rcp(var + EPSV);
                        v.x = var * rr; v.y = mean * (EPSV * rr);
                    }
                    if (okab1) {
                        float mean = st.S1[1] * INV_KK;
                        float var  = st.S2[1] * INV_KK - mean * mean;
                        float rr   = fast_rcp(var + EPSV);
                        v.z = var * rr; v.w = mean * (EPSV * rr);
                    }
                }
                abw[r * ABP] = v;
            }
            slot = (slot + 1 == 11) ? 0 : slot + 1;
        }
    }

    // ================= P3a: batch i-1 + f + loss ===========================
    if (isB) {
        const float* xp = xin[p3p];
        const int    cx = c0 + 2 * p3i;
        float2 xv[4];
#pragma unroll
        for (int r = 0; r < RPB; ++r) {
            const int yo = Rb - 14 + r;
            xv[r] = (STEADY || (yo >= y0 && yo < y0 + band))
                  ? __ldg((const float2*)(xp + (size_t)yo * WD + cx))
                  : make_float2(0.f, 0.f);
        }
        if (p3p == 2) {
            const float2* fa  = fb2 + (((i - 1) & 1) * 2 + 0) * (RPB * CTP) + p3i;
            const float2* fbv = fb2 + (((i - 1) & 1) * 2 + 1) * (RPB * CTP) + p3i;
#pragma unroll
            for (int r = 0; r < RPB; ++r) {
                const int yr = 4 * i - 28 + r;
                if (STEADY || (yr >= 0 && yr < band)) {
                    float2 a01 = fa[r * CTP];
                    float2 b01 = fbv[r * CTP];
                    st.lacc += fabsf(st.f2s[r].x - fmaxf(a01.x, b01.x));
                    st.lacc += fabsf(st.f2s[r].y - fmaxf(a01.y, b01.y));
                }
            }
        }
        const float4* abr = ab4 + ((i - 1) & 1) * (3 * RPB * ABP)
                            + (p3p * RPB) * ABP + p3i;
        int slot = (Rb + 13) % 11;                 // slot(ya), ya = Rb-9+r
#pragma unroll
        for (int r = 0; r < RPB; ++r) {
            const int yb = Rb - 4 + r;
            if (STEADY || (yb >= y0 && yb <= y0 + band + 9)) {
                const int ya = yb - 5;
                const float4* ap = abr + r * ABP;
                float4 w0 = ap[0], w1 = ap[1], w2 = ap[2];
                float4 w3 = ap[3], w4 = ap[4], w5 = ap[5];
                float h1 = ((w0.x + w0.z) + (w1.x + w1.z))
                         + ((w2.x + w2.z) + (w3.x + w3.z))
                         + ((w4.x + w4.z) + (w5.x + w5.z));
                float h2 = ((w0.y + w0.w) + (w1.y + w1.w))
                         + ((w2.y + w2.w) + (w3.y + w3.w))
                         + ((w4.y + w4.w) + (w5.y + w5.w));
                const float h1a = h1 - w5.z, h2a = h2 - w5.w;
                const float h1b = h1 - w0.x, h2b = h2 - w0.y;
                float4* rp = &hac4[(p3p * 11 + slot) * CTP + p3i];
                if (STEADY || ya >= y0 + 6) {
                    float4 o = *rp;
                    st.T1[0] -= o.x; st.T2[0] -= o.y; st.T1[1] -= o.z; st.T2[1] -= o.w;
                }
                *rp = make_float4(h1a, h2a, h1b, h2b);
                st.T1[0] += h1a; st.T2[0] += h2a; st.T1[1] += h1b; st.T2[1] += h2b;
                const int yo = ya - 5;
                if (STEADY || (yo >= y0 && yo < y0 + band)) {
                    float ma0 = st.T1[0] * INV_KK, mb0 = st.T2[0] * INV_KK;
                    float ma1 = st.T1[1] * INV_KK, mb1 = st.T2[1] * INV_KK;
                    float2 xr = xv[r];
                    float f0 = xr.x - fmaf(ma0, xr.x, mb0);
                    float f1 = xr.y - fmaf(ma1, xr.y, mb1);
                    if (p3p < 2) {
                        fb2[(((i & 1) * 2 + p3p) * RPB + r) * CTP + p3i] =
                            make_float2(fabsf(f0), fabsf(f1));
                    } else {
                        st.f2s[r] = make_float2(f0, f1);
                    }
                }
            }
            slot = (slot + 1 == 11) ? 0 : slot + 1;
        }
    }
    __syncthreads();
}

__global__ void __launch_bounds__(NTH, 2) fused_loss(
    const float* __restrict__ gen, const float* __restrict__ ir,
    const float* __restrict__ vi, float* __restrict__ out)
{
    extern __shared__ float smf[];
    const int t    = threadIdx.x;
    const int c0   = blockIdx.x * CT;
    const int y0   = blockIdx.y * BANDA;
    const int band = (blockIdx.y == 2) ? (HT - 2 * BANDA) : BANDA;
    const size_t pbase = (size_t)blockIdx.z * EPLANE;
    const float* xin[3] = { ir + pbase, vi + pbase, gen + pbase };

    float4* hc4  = (float4*)(smf + OFF_HC);        // [p][slot11][ABP]
    float4* ab4  = (float4*)(smf + OFF_AB);        // [buf][p][r][ABP]
    float4* hac4 = (float4*)(smf + OFF_HAC);       // [p][slot11][CTP]
    float2* fb2  = (float2*)(smf + OFF_FB);        // [buf][p01][r][CTP]
    float*  red  = smf + OFF_RED;

    // roles: P2 = threads 0..206, P3a = threads 224..415
    const bool isA = t < 3 * ABP;                  // 207 threads
    const int  p2p = t / ABP;
    const int  p2j = t - p2p * ABP;
    const int  tb  = t - 224;
    const bool isB = (tb >= 0) && (tb < 3 * CTP);  // 192 threads
    const int  p3p = tb >> 6;
    const int  p3i = tb & (CTP - 1);

    // thread-invariant column predicates
    const int cbase = c0 - 10 + 2 * p2j;
    const bool okc0 = (unsigned)(cbase)      < (unsigned)WD;
    const bool okc1 = (unsigned)(cbase + 2)  < (unsigned)WD;
    const bool okc2 = (unsigned)(cbase + 4)  < (unsigned)WD;
    const bool okc3 = (unsigned)(cbase + 6)  < (unsigned)WD;
    const bool okc4 = (unsigned)(cbase + 8)  < (unsigned)WD;
    const bool okc5 = (unsigned)(cbase + 10) < (unsigned)WD;
    const int  cab  = c0 - 5 + 2 * p2j;
    const bool okab0 = (unsigned)cab       < (unsigned)WD;
    const bool okab1 = (unsigned)(cab + 1) < (unsigned)WD;

    IterState st;
    st.S1[0] = st.S1[1] = st.S2[0] = st.S2[1] = 0.f;
    st.T1[0] = st.T1[1] = st.T2[0] = st.T2[1] = 0.f;
#pragma unroll
    for (int r = 0; r < 4; ++r) st.f2s[r] = make_float2(0.f, 0.f);
    st.lacc = 0.f;

    const int iters = (band + 24) / RPB + 1;       // 50 or 49
    const int pmax  = (band + 20) / RPB;           // P2 active while i < pmax
    int iSteadyEnd  = (HT - y0 + 6) / 4 + 1;       // last-band row-bound
    if (iSteadyEnd > pmax) iSteadyEnd = pmax;
    if (iSteadyEnd < 7)    iSteadyEnd = 7;

    for (int i = 0; i < 7; ++i)
        iter_body<false>(i, y0, band, c0, pmax, isA, p2p, p2j, isB, p3p, p3i,
                         okc0, okc1, okc2, okc3, okc4, okc5, okab0, okab1,
                         xin, hc4, ab4, hac4, fb2, st);
    for (int i = 7; i < iSteadyEnd; ++i)
        iter_body<true>(i, y0, band, c0, pmax, isA, p2p, p2j, isB, p3p, p3i,
                        okc0, okc1, okc2, okc3, okc4, okc5, okab0, okab1,
                        xin, hc4, ab4, hac4, fb2, st);
    for (int i = iSteadyEnd; i < iters; ++i)
        iter_body<false>(i, y0, band, c0, pmax, isA, p2p, p2j, isB, p3p, p3i,
                         okc0, okc1, okc2, okc3, okc4, okc5, okab0, okab1,
                         xin, hc4, ab4, hac4, fb2, st);

    // ---- block reduction + atomic ----------------------------------------
    float lacc = st.lacc;
#pragma unroll
    for (int o = 16; o; o >>= 1) lacc += __shfl_down_sync(0xffffffffu, lacc, o);
    if ((t & 31) == 0) red[t >> 5] = lacc;
    __syncthreads();
    if (t == 0) {
        float v = 0.f;
#pragma unroll
        for (int w = 0; w < NWARP; ++w) v += red[w];
        atomicAdd(out, v * SCALE);
    }
}

__global__ void zero_out(float* out) { out[0] = 0.f; }

// ---------------------------------------------------------------------------
extern "C" void kernel_launch(void* const* d_in, const int* in_sizes, int n_in,
                              void* d_out, int out_size) {
    const float* gen = (const float*)d_in[0];
    const float* ir  = (const float*)d_in[1];
    const float* vi  = (const float*)d_in[2];
    float* out = (float*)d_out;

    cudaFuncSetAttribute(fused_loss, cudaFuncAttributeMaxDynamicSharedMemorySize,
                         SMEM_BYTES);

    zero_out<<<1, 1>>>(out);
    dim3 grid(WD / CT, 3, NPL);   // (4, 3, 24) = 288 blocks
    fused_loss<<<grid, NTH, SMEM_BYTES>>>(gen, ir, vi, out);
}